// round 1
// baseline (speedup 1.0000x reference)
#include <cuda_runtime.h>
#include <cstdint>

// ---------------- problem constants ----------------
#define B_    4
#define L_    1024
#define N_    2048
#define VD_   512
#define LD_   768
#define HID_  512
#define H_    8
#define HD_   64
#define SCALE_ 0.125f   // 64^-0.5

// ---------------- scratch (no allocations allowed) ----------------
__device__ float g_q [(size_t)B_ * L_ * HID_];        // [B*L, HID]  (pre-scaled Q)
__device__ float g_kv[(size_t)B_ * N_ * 2 * HID_];    // [B*N, 2*HID] (k | v)
__device__ float g_ao[(size_t)B_ * L_ * HID_];        // attention out [B*L, HID]

// ---------------- helpers ----------------
__device__ __forceinline__ float to_tf32(float x) {
    uint32_t u;
    asm("cvt.rna.tf32.f32 %0, %1;" : "=r"(u) : "f"(x));
    return __uint_as_float(u);
}

__device__ __forceinline__ void mma_tf32(float* c, const uint32_t* a, const uint32_t* b) {
    asm volatile(
        "mma.sync.aligned.m16n8k8.row.col.f32.tf32.tf32.f32 "
        "{%0,%1,%2,%3}, {%4,%5,%6,%7}, {%8,%9}, {%0,%1,%2,%3};"
        : "+f"(c[0]), "+f"(c[1]), "+f"(c[2]), "+f"(c[3])
        : "r"(a[0]), "r"(a[1]), "r"(a[2]), "r"(a[3]), "r"(b[0]), "r"(b[1]));
}

// ======================================================================
// GEMM: C[M,N] = alpha * A[M,K] @ W[N,K]^T (+ bias[N])
// A row-major, W row-major [N,K]  -> mma row.col directly.
// 128x128x32 tile, 256 threads (8 warps as 2x4, warp tile 64x32).
// ======================================================================
#define GBM 128
#define GBN 128
#define GBK 32
#define GST 36   // 36 % 32 == 4 -> conflict-free fragment loads (4g + t4)

__global__ void __launch_bounds__(256, 2)
gemm_tf32_kernel(const float* __restrict__ A, const float* __restrict__ W,
                 float* __restrict__ C, const float* __restrict__ bias,
                 int M, int N, int K, float alpha)
{
    __shared__ float As[GBM * GST];
    __shared__ float Bs[GBN * GST];

    const int tid  = threadIdx.x;
    const int lane = tid & 31;
    const int w    = tid >> 5;
    const int g    = lane >> 2;
    const int t4   = lane & 3;
    const int wm   = w >> 2;   // 0..1
    const int wn   = w & 3;    // 0..3
    const int bm0  = blockIdx.y * GBM;
    const int bn0  = blockIdx.x * GBN;

    float acc[4][4][4];
    #pragma unroll
    for (int mi = 0; mi < 4; mi++)
        #pragma unroll
        for (int ni = 0; ni < 4; ni++)
            #pragma unroll
            for (int j = 0; j < 4; j++) acc[mi][ni][j] = 0.f;

    const int lr = tid >> 3;        // 0..31 (row within 32-row pass)
    const int lc = (tid & 7) * 4;   // 0..28 (col, float4)

    for (int k0 = 0; k0 < K; k0 += GBK) {
        #pragma unroll
        for (int i = 0; i < 4; i++) {
            int r = lr + i * 32;
            float4 va = *reinterpret_cast<const float4*>(A + (size_t)(bm0 + r) * K + k0 + lc);
            float4 vb = *reinterpret_cast<const float4*>(W + (size_t)(bn0 + r) * K + k0 + lc);
            float* pa = As + r * GST + lc;
            pa[0] = to_tf32(va.x); pa[1] = to_tf32(va.y); pa[2] = to_tf32(va.z); pa[3] = to_tf32(va.w);
            float* pb = Bs + r * GST + lc;
            pb[0] = to_tf32(vb.x); pb[1] = to_tf32(vb.y); pb[2] = to_tf32(vb.z); pb[3] = to_tf32(vb.w);
        }
        __syncthreads();

        #pragma unroll
        for (int kk = 0; kk < GBK / 8; kk++) {
            uint32_t af[4][4], bf[4][2];
            #pragma unroll
            for (int mi = 0; mi < 4; mi++) {
                int rb = wm * 64 + mi * 16;
                af[mi][0] = __float_as_uint(As[(rb + g)     * GST + kk * 8 + t4]);
                af[mi][1] = __float_as_uint(As[(rb + 8 + g) * GST + kk * 8 + t4]);
                af[mi][2] = __float_as_uint(As[(rb + g)     * GST + kk * 8 + t4 + 4]);
                af[mi][3] = __float_as_uint(As[(rb + 8 + g) * GST + kk * 8 + t4 + 4]);
            }
            #pragma unroll
            for (int ni = 0; ni < 4; ni++) {
                int nb = wn * 32 + ni * 8;
                bf[ni][0] = __float_as_uint(Bs[(nb + g) * GST + kk * 8 + t4]);
                bf[ni][1] = __float_as_uint(Bs[(nb + g) * GST + kk * 8 + t4 + 4]);
            }
            #pragma unroll
            for (int mi = 0; mi < 4; mi++)
                #pragma unroll
                for (int ni = 0; ni < 4; ni++)
                    mma_tf32(acc[mi][ni], af[mi], bf[ni]);
        }
        __syncthreads();
    }

    #pragma unroll
    for (int mi = 0; mi < 4; mi++) {
        int r0 = bm0 + wm * 64 + mi * 16 + g;
        #pragma unroll
        for (int ni = 0; ni < 4; ni++) {
            int col = bn0 + wn * 32 + ni * 8 + 2 * t4;
            float b0 = 0.f, b1 = 0.f;
            if (bias) { b0 = bias[col]; b1 = bias[col + 1]; }
            float2 v0 = make_float2(acc[mi][ni][0] * alpha + b0, acc[mi][ni][1] * alpha + b1);
            float2 v1 = make_float2(acc[mi][ni][2] * alpha + b0, acc[mi][ni][3] * alpha + b1);
            *reinterpret_cast<float2*>(C + (size_t)r0       * N + col) = v0;
            *reinterpret_cast<float2*>(C + (size_t)(r0 + 8) * N + col) = v1;
        }
    }
}

// ======================================================================
// Flash attention with streamed mask.
// Grid (L/128, H, B); 256 threads = 8 warps; warp w owns rows [16w,16w+16).
// Per N-tile (128 keys): load K,V(T) tiles -> S = Q K^T (tf32 mma)
// -> += mask (global float2, sector-aligned) -> online softmax
// -> P to smem (aliased over K tile) -> O += P V (tf32 mma).
// ======================================================================
#define QST 68
#define KST 68
#define PST 132
#define VST 132
#define U_FLOATS (8 * 16 * PST)                    // 16896 (>= 128*KST = 8704)
#define ATTN_SMEM_FLOATS (128 * QST + U_FLOATS + 64 * VST)
#define ATTN_SMEM_BYTES  (ATTN_SMEM_FLOATS * 4)    // 136192

__global__ void __launch_bounds__(256, 1)
attn_kernel(const float* __restrict__ q, const float* __restrict__ kv,
            const float* __restrict__ mask, float* __restrict__ out)
{
    extern __shared__ float sm[];
    float* Qs = sm;
    float* U  = sm + 128 * QST;    // K tile, later reused as P
    float* VT = U + U_FLOATS;      // V transposed [64][128]

    const int tid  = threadIdx.x;
    const int lane = tid & 31;
    const int w    = tid >> 5;
    const int g    = lane >> 2;
    const int t4   = lane & 3;
    const int b     = blockIdx.z;
    const int h     = blockIdx.y;
    const int mbase = blockIdx.x * 128;
    float* Pw = U + w * (16 * PST);

    // ---- load Q tile (already scaled by 1/sqrt(HD)) ----
    const float* qb = q + ((size_t)(b * L_ + mbase)) * HID_ + h * HD_;
    {
        const int r0 = tid >> 4;
        const int d  = (tid & 15) * 4;
        #pragma unroll
        for (int i = 0; i < 8; i++) {
            int r = r0 + i * 16;
            float4 v = *reinterpret_cast<const float4*>(qb + (size_t)r * HID_ + d);
            float* p = Qs + r * QST + d;
            p[0] = to_tf32(v.x); p[1] = to_tf32(v.y); p[2] = to_tf32(v.z); p[3] = to_tf32(v.w);
        }
    }
    __syncthreads();

    const int row0 = w * 16 + g;
    uint32_t qa[8][4];
    #pragma unroll
    for (int k8 = 0; k8 < 8; k8++) {
        qa[k8][0] = __float_as_uint(Qs[row0       * QST + k8 * 8 + t4]);
        qa[k8][1] = __float_as_uint(Qs[(row0 + 8) * QST + k8 * 8 + t4]);
        qa[k8][2] = __float_as_uint(Qs[row0       * QST + k8 * 8 + t4 + 4]);
        qa[k8][3] = __float_as_uint(Qs[(row0 + 8) * QST + k8 * 8 + t4 + 4]);
    }

    float m0 = -1e30f, m1 = -1e30f, l0 = 0.f, l1 = 0.f;
    float o[8][4];
    #pragma unroll
    for (int df = 0; df < 8; df++)
        #pragma unroll
        for (int j = 0; j < 4; j++) o[df][j] = 0.f;

    const float* mrow = mask + (((size_t)(b * H_ + h)) * L_ + mbase + row0) * N_ + 2 * t4;
    const float* kvb  = kv + ((size_t)b * N_) * (2 * HID_) + h * HD_;

    for (int nt = 0; nt < N_ / 128; nt++) {
        const size_t nb = (size_t)nt * 128;
        __syncthreads();   // prev-iter P/VT consumers done before overwrite

        // ---- load K tile (into U) and V tile transposed (into VT) ----
        {
            const int r0l = tid >> 4;
            const int d   = (tid & 15) * 4;
            #pragma unroll
            for (int i = 0; i < 8; i++) {
                int r = r0l + i * 16;
                const float* src = kvb + (nb + r) * (2 * HID_) + d;
                float4 kk = *reinterpret_cast<const float4*>(src);
                float* p = U + r * KST + d;
                p[0] = to_tf32(kk.x); p[1] = to_tf32(kk.y); p[2] = to_tf32(kk.z); p[3] = to_tf32(kk.w);
                float4 vv = *reinterpret_cast<const float4*>(src + HID_);
                VT[(d + 0) * VST + r] = to_tf32(vv.x);
                VT[(d + 1) * VST + r] = to_tf32(vv.y);
                VT[(d + 2) * VST + r] = to_tf32(vv.z);
                VT[(d + 3) * VST + r] = to_tf32(vv.w);
            }
        }
        __syncthreads();

        // ---- S = Q K^T ----
        float s[16][4];
        #pragma unroll
        for (int nf = 0; nf < 16; nf++) {
            s[nf][0] = 0.f; s[nf][1] = 0.f; s[nf][2] = 0.f; s[nf][3] = 0.f;
            #pragma unroll
            for (int k8 = 0; k8 < 8; k8++) {
                uint32_t bf[2];
                bf[0] = __float_as_uint(U[(nf * 8 + g) * KST + k8 * 8 + t4]);
                bf[1] = __float_as_uint(U[(nf * 8 + g) * KST + k8 * 8 + t4 + 4]);
                mma_tf32(s[nf], qa[k8], bf);
            }
        }

        // ---- += mask (streamed from HBM), tile row-max ----
        float tm0 = -1e30f, tm1 = -1e30f;
        const float* mp = mrow + nb;
        #pragma unroll
        for (int nf = 0; nf < 16; nf++) {
            float2 ma  = *reinterpret_cast<const float2*>(mp + nf * 8);
            float2 mbv = *reinterpret_cast<const float2*>(mp + (size_t)8 * N_ + nf * 8);
            s[nf][0] += ma.x;  s[nf][1] += ma.y;
            s[nf][2] += mbv.x; s[nf][3] += mbv.y;
            tm0 = fmaxf(tm0, fmaxf(s[nf][0], s[nf][1]));
            tm1 = fmaxf(tm1, fmaxf(s[nf][2], s[nf][3]));
        }
        tm0 = fmaxf(tm0, __shfl_xor_sync(0xffffffffu, tm0, 1));
        tm0 = fmaxf(tm0, __shfl_xor_sync(0xffffffffu, tm0, 2));
        tm1 = fmaxf(tm1, __shfl_xor_sync(0xffffffffu, tm1, 1));
        tm1 = fmaxf(tm1, __shfl_xor_sync(0xffffffffu, tm1, 2));

        float nm0 = fmaxf(m0, tm0), nm1 = fmaxf(m1, tm1);
        float al0 = __expf(m0 - nm0), al1 = __expf(m1 - nm1);
        m0 = nm0; m1 = nm1;

        float rs0 = 0.f, rs1 = 0.f;
        #pragma unroll
        for (int nf = 0; nf < 16; nf++) {
            s[nf][0] = __expf(s[nf][0] - nm0);
            s[nf][1] = __expf(s[nf][1] - nm0);
            s[nf][2] = __expf(s[nf][2] - nm1);
            s[nf][3] = __expf(s[nf][3] - nm1);
            rs0 += s[nf][0] + s[nf][1];
            rs1 += s[nf][2] + s[nf][3];
        }
        rs0 += __shfl_xor_sync(0xffffffffu, rs0, 1);
        rs0 += __shfl_xor_sync(0xffffffffu, rs0, 2);
        rs1 += __shfl_xor_sync(0xffffffffu, rs1, 1);
        rs1 += __shfl_xor_sync(0xffffffffu, rs1, 2);
        l0 = l0 * al0 + rs0;
        l1 = l1 * al1 + rs1;
        #pragma unroll
        for (int df = 0; df < 8; df++) {
            o[df][0] *= al0; o[df][1] *= al0;
            o[df][2] *= al1; o[df][3] *= al1;
        }

        __syncthreads();   // all warps done reading K -> safe to overwrite with P

        // ---- P to smem (per-warp region), then O += P V ----
        #pragma unroll
        for (int nf = 0; nf < 16; nf++) {
            float2 p0 = make_float2(to_tf32(s[nf][0]), to_tf32(s[nf][1]));
            float2 p1 = make_float2(to_tf32(s[nf][2]), to_tf32(s[nf][3]));
            *reinterpret_cast<float2*>(Pw + g       * PST + nf * 8 + 2 * t4) = p0;
            *reinterpret_cast<float2*>(Pw + (g + 8) * PST + nf * 8 + 2 * t4) = p1;
        }
        __syncwarp();

        #pragma unroll
        for (int k8 = 0; k8 < 16; k8++) {
            uint32_t pa[4];
            pa[0] = __float_as_uint(Pw[g       * PST + k8 * 8 + t4]);
            pa[1] = __float_as_uint(Pw[(g + 8) * PST + k8 * 8 + t4]);
            pa[2] = __float_as_uint(Pw[g       * PST + k8 * 8 + t4 + 4]);
            pa[3] = __float_as_uint(Pw[(g + 8) * PST + k8 * 8 + t4 + 4]);
            #pragma unroll
            for (int df = 0; df < 8; df++) {
                uint32_t bf[2];
                bf[0] = __float_as_uint(VT[(df * 8 + g) * VST + k8 * 8 + t4]);
                bf[1] = __float_as_uint(VT[(df * 8 + g) * VST + k8 * 8 + t4 + 4]);
                mma_tf32(o[df], pa, bf);
            }
        }
    }

    // ---- normalize and write [b, l, h*64+d] ----
    float inv0 = 1.f / l0, inv1 = 1.f / l1;
    float* ob = out + ((size_t)(b * L_ + mbase + row0)) * HID_ + h * HD_;
    #pragma unroll
    for (int df = 0; df < 8; df++) {
        int col = df * 8 + 2 * t4;
        *reinterpret_cast<float2*>(ob + col)                    = make_float2(o[df][0] * inv0, o[df][1] * inv0);
        *reinterpret_cast<float2*>(ob + (size_t)8 * HID_ + col) = make_float2(o[df][2] * inv1, o[df][3] * inv1);
    }
}

// ======================================================================
extern "C" void kernel_launch(void* const* d_in, const int* in_sizes, int n_in,
                              void* d_out, int out_size)
{
    (void)in_sizes; (void)n_in; (void)out_size;
    const float* x     = (const float*)d_in[0];
    const float* vf    = (const float*)d_in[1];
    const float* mask  = (const float*)d_in[2];
    const float* Wq    = (const float*)d_in[3];
    const float* Wkv   = (const float*)d_in[4];
    const float* Wproj = (const float*)d_in[5];
    const float* bproj = (const float*)d_in[6];
    float* out = (float*)d_out;

    float *qbuf, *kvbuf, *aobuf;
    cudaGetSymbolAddress((void**)&qbuf,  g_q);
    cudaGetSymbolAddress((void**)&kvbuf, g_kv);
    cudaGetSymbolAddress((void**)&aobuf, g_ao);

    // Q = SCALE * x @ Wq^T          [4096, 512]
    gemm_tf32_kernel<<<dim3(HID_ / GBN, (B_ * L_) / GBM), 256>>>(
        x, Wq, qbuf, nullptr, B_ * L_, HID_, VD_, SCALE_);

    // KV = vfeats @ Wkv^T           [8192, 1024]
    gemm_tf32_kernel<<<dim3((2 * HID_) / GBN, (B_ * N_) / GBM), 256>>>(
        vf, Wkv, kvbuf, nullptr, B_ * N_, 2 * HID_, LD_, 1.0f);

    // Fused attention (mask streamed, softmax online)
    cudaFuncSetAttribute(attn_kernel, cudaFuncAttributeMaxDynamicSharedMemorySize, ATTN_SMEM_BYTES);
    attn_kernel<<<dim3(L_ / 128, H_, B_), 256, ATTN_SMEM_BYTES>>>(qbuf, kvbuf, mask, aobuf);

    // out = AO @ Wproj^T + bproj    [4096, 512]
    gemm_tf32_kernel<<<dim3(VD_ / GBN, (B_ * L_) / GBM), 256>>>(
        aobuf, Wproj, out, bproj, B_ * L_, VD_, HID_, 1.0f);
}

// round 3
// speedup vs baseline: 1.2587x; 1.2587x over previous
#include <cuda_runtime.h>
#include <cstdint>

// ---------------- problem constants ----------------
#define B_    4
#define L_    1024
#define N_    2048
#define VD_   512
#define LD_   768
#define HID_  512
#define H_    8
#define HD_   64
#define SCALE_ 0.125f   // 64^-0.5

// ---------------- scratch ----------------
__device__ float g_q [(size_t)B_ * L_ * HID_];
__device__ float g_kv[(size_t)B_ * N_ * 2 * HID_];
__device__ float g_ao[(size_t)B_ * L_ * HID_];

// ---------------- helpers ----------------
__device__ __forceinline__ uint32_t f2tf32(float x) {
    uint32_t u;
    asm("cvt.rna.tf32.f32 %0, %1;" : "=r"(u) : "f"(x));
    return u;
}
__device__ __forceinline__ float f2tf32f(float x) { return __uint_as_float(f2tf32(x)); }

__device__ __forceinline__ void mma_tf32(float* c, const uint32_t* a, const uint32_t* b) {
    asm volatile(
        "mma.sync.aligned.m16n8k8.row.col.f32.tf32.tf32.f32 "
        "{%0,%1,%2,%3}, {%4,%5,%6,%7}, {%8,%9}, {%0,%1,%2,%3};"
        : "+f"(c[0]), "+f"(c[1]), "+f"(c[2]), "+f"(c[3])
        : "r"(a[0]), "r"(a[1]), "r"(a[2]), "r"(a[3]), "r"(b[0]), "r"(b[1]));
}

__device__ __forceinline__ void cp16(uint32_t dst, const float* src) {
    asm volatile("cp.async.cg.shared.global [%0], [%1], 16;" :: "r"(dst), "l"(src));
}
__device__ __forceinline__ void cp_commit() { asm volatile("cp.async.commit_group;"); }
template <int Np>
__device__ __forceinline__ void cp_wait() {
    asm volatile("cp.async.wait_group %0;" :: "n"(Np) : "memory");
}

// ======================================================================
// GEMM body: C = alpha * A[M,K] @ W[N,K]^T (+bias), cp.async 2-stage
// pipeline, tf32 cvt in registers, optional tf32 rounding of output.
// 128x128x32 tile, 256 threads (8 warps 2x4, warp tile 64x32).
// ======================================================================
#define GBM 128
#define GBN 128
#define GBK 32
#define GST 36                 // 36 % 32 == 4 -> conflict-free frag loads
#define GSTAGE (128 * GST)
#define GEMM_SMEM_BYTES (4 * GSTAGE * 4)   // 73728

__device__ __forceinline__ void gemm_body(
    const float* __restrict__ A, const float* __restrict__ W,
    float* __restrict__ C, const float* __restrict__ bias,
    int M, int Nn, int K, float alpha, int round_out,
    int bx, int by, float* sm)
{
    float* As = sm;
    float* Bs = sm + 2 * GSTAGE;
    const int tid  = threadIdx.x;
    const int lane = tid & 31;
    const int w    = tid >> 5;
    const int g    = lane >> 2;
    const int t4   = lane & 3;
    const int wm   = w >> 2;
    const int wn   = w & 3;
    const int bm0  = by * GBM;
    const int bn0  = bx * GBN;
    const int KT   = K / GBK;
    const uint32_t sA = (uint32_t)__cvta_generic_to_shared(As);
    const uint32_t sB = (uint32_t)__cvta_generic_to_shared(Bs);

    float acc[4][4][4];
    #pragma unroll
    for (int mi = 0; mi < 4; mi++)
        #pragma unroll
        for (int ni = 0; ni < 4; ni++)
            #pragma unroll
            for (int j = 0; j < 4; j++) acc[mi][ni][j] = 0.f;

    auto issue = [&](int kt, int st) {
        const int k0 = kt * GBK;
        #pragma unroll
        for (int i = 0; i < 4; i++) {
            int c   = tid + 256 * i;      // 0..1023
            int row = c >> 3;             // 0..127
            int ch  = (c & 7) * 4;        // 0..28
            cp16(sA + (uint32_t)(st * GSTAGE + row * GST + ch) * 4,
                 A + (size_t)(bm0 + row) * K + k0 + ch);
            cp16(sB + (uint32_t)(st * GSTAGE + row * GST + ch) * 4,
                 W + (size_t)(bn0 + row) * K + k0 + ch);
        }
        cp_commit();
    };

    issue(0, 0);
    issue(1, 1);

    for (int kt = 0; kt < KT; kt++) {
        if (kt < KT - 1) cp_wait<1>(); else cp_wait<0>();
        __syncthreads();
        const float* Ast = As + (kt & 1) * GSTAGE;
        const float* Bst = Bs + (kt & 1) * GSTAGE;

        #pragma unroll
        for (int kk = 0; kk < GBK / 8; kk++) {
            uint32_t af[4][4], bf[4][2];
            #pragma unroll
            for (int mi = 0; mi < 4; mi++) {
                int rb = wm * 64 + mi * 16;
                af[mi][0] = f2tf32(Ast[(rb + g)     * GST + kk * 8 + t4]);
                af[mi][1] = f2tf32(Ast[(rb + 8 + g) * GST + kk * 8 + t4]);
                af[mi][2] = f2tf32(Ast[(rb + g)     * GST + kk * 8 + t4 + 4]);
                af[mi][3] = f2tf32(Ast[(rb + 8 + g) * GST + kk * 8 + t4 + 4]);
            }
            #pragma unroll
            for (int ni = 0; ni < 4; ni++) {
                int nb = wn * 32 + ni * 8;
                bf[ni][0] = f2tf32(Bst[(nb + g) * GST + kk * 8 + t4]);
                bf[ni][1] = f2tf32(Bst[(nb + g) * GST + kk * 8 + t4 + 4]);
            }
            #pragma unroll
            for (int mi = 0; mi < 4; mi++)
                #pragma unroll
                for (int ni = 0; ni < 4; ni++)
                    mma_tf32(acc[mi][ni], af[mi], bf[ni]);
        }
        __syncthreads();
        if (kt + 2 < KT) issue(kt + 2, kt & 1);
    }

    #pragma unroll
    for (int mi = 0; mi < 4; mi++) {
        int r0 = bm0 + wm * 64 + mi * 16 + g;
        #pragma unroll
        for (int ni = 0; ni < 4; ni++) {
            int col = bn0 + wn * 32 + ni * 8 + 2 * t4;
            float b0 = 0.f, b1 = 0.f;
            if (bias) { b0 = bias[col]; b1 = bias[col + 1]; }
            float e0 = acc[mi][ni][0] * alpha + b0;
            float e1 = acc[mi][ni][1] * alpha + b1;
            float e2 = acc[mi][ni][2] * alpha + b0;
            float e3 = acc[mi][ni][3] * alpha + b1;
            if (round_out) {
                e0 = f2tf32f(e0); e1 = f2tf32f(e1);
                e2 = f2tf32f(e2); e3 = f2tf32f(e3);
            }
            *reinterpret_cast<float2*>(C + (size_t)r0       * Nn + col) = make_float2(e0, e1);
            *reinterpret_cast<float2*>(C + (size_t)(r0 + 8) * Nn + col) = make_float2(e2, e3);
        }
    }
}

// Q-proj (128 blocks) + KV-proj (512 blocks) merged into one launch.
__global__ void __launch_bounds__(256, 2)
qkv_proj_kernel(const float* __restrict__ x, const float* __restrict__ Wq, float* __restrict__ qout,
                const float* __restrict__ vf, const float* __restrict__ Wkv, float* __restrict__ kvout)
{
    extern __shared__ float sm[];
    int bid = blockIdx.x;
    if (bid < 128) {
        gemm_body(x, Wq, qout, nullptr, B_ * L_, HID_, VD_, SCALE_, 1,
                  bid & 3, bid >> 2, sm);
    } else {
        bid -= 128;
        gemm_body(vf, Wkv, kvout, nullptr, B_ * N_, 2 * HID_, LD_, 1.0f, 1,
                  bid & 7, bid >> 3, sm);
    }
}

__global__ void __launch_bounds__(256, 2)
proj_kernel(const float* __restrict__ A, const float* __restrict__ W,
            float* __restrict__ C, const float* __restrict__ bias)
{
    extern __shared__ float sm[];
    gemm_body(A, W, C, bias, B_ * L_, VD_, HID_, 1.0f, 0,
              blockIdx.x & 3, blockIdx.x >> 2, sm);
}

// ======================================================================
// Flash attention: cp.async double-buffered K/V, mask prefetched to regs.
// P tile aliased over the dead Q region; AV done in two 64-key halves so
// each warp's P half (16 x 68-stride, cols<=64) fits exactly: 8*1088=8704.
// ======================================================================
#define QSTR 68
#define KSTR 68
#define VSTR 72
#define PSTR 68                       // half-P stride (64 cols + pad)
#define OF_K 8704                     // Q/P region = 128*68
#define KTILE 8704
#define OF_V (OF_K + 2 * KTILE)       // 26112
#define VTILE 9216                    // 128*72
#define ATTN_SMEM_FLOATS (OF_V + 2 * VTILE)     // 44544
#define ATTN_SMEM_BYTES  (ATTN_SMEM_FLOATS * 4) // 178176

__global__ void __launch_bounds__(256, 1)
attn_kernel(const float* __restrict__ q, const float* __restrict__ kv,
            const float* __restrict__ mask, float* __restrict__ out)
{
    extern __shared__ float sm[];
    float* Qs = sm;
    const uint32_t sbase = (uint32_t)__cvta_generic_to_shared(sm);

    const int tid  = threadIdx.x;
    const int lane = tid & 31;
    const int w    = tid >> 5;
    const int g    = lane >> 2;
    const int t4   = lane & 3;
    const int b     = blockIdx.z;
    const int h     = blockIdx.y;
    const int mbase = blockIdx.x * 128;

    const float* qb  = q  + ((size_t)(b * L_ + mbase)) * HID_ + h * HD_;
    const float* kvb = kv + ((size_t)b * N_) * (2 * HID_) + h * HD_;

    // ---- prologue: async Q tile + first two K/V tiles ----
    #pragma unroll
    for (int i = 0; i < 8; i++) {
        int c   = tid + 256 * i;   // 0..2047
        int row = c >> 4;          // 0..127
        int ch  = (c & 15) * 4;    // 0..60
        cp16(sbase + (uint32_t)(row * QSTR + ch) * 4, qb + (size_t)row * HID_ + ch);
    }
    cp_commit();

    auto issueKV = [&](int nt, int st) {
        const size_t nb = (size_t)nt * 128;
        #pragma unroll
        for (int i = 0; i < 8; i++) {
            int c   = tid + 256 * i;
            int row = c >> 4;
            int ch  = (c & 15) * 4;
            const float* src = kvb + (nb + row) * (2 * HID_) + ch;
            cp16(sbase + (uint32_t)(OF_K + st * KTILE + row * KSTR + ch) * 4, src);
            cp16(sbase + (uint32_t)(OF_V + st * VTILE + row * VSTR + ch) * 4, src + HID_);
        }
        cp_commit();
    };
    issueKV(0, 0);
    issueKV(1, 1);

    // ---- wait for Q, build Q fragments (Q region then becomes P) ----
    cp_wait<2>();
    __syncthreads();

    const int row0 = w * 16 + g;
    uint32_t qa[8][4];
    #pragma unroll
    for (int k8 = 0; k8 < 8; k8++) {
        qa[k8][0] = __float_as_uint(Qs[row0       * QSTR + k8 * 8 + t4]);
        qa[k8][1] = __float_as_uint(Qs[(row0 + 8) * QSTR + k8 * 8 + t4]);
        qa[k8][2] = __float_as_uint(Qs[row0       * QSTR + k8 * 8 + t4 + 4]);
        qa[k8][3] = __float_as_uint(Qs[(row0 + 8) * QSTR + k8 * 8 + t4 + 4]);
    }

    float m0 = -1e30f, m1 = -1e30f, l0 = 0.f, l1 = 0.f;
    float o[8][4];
    #pragma unroll
    for (int df = 0; df < 8; df++)
        #pragma unroll
        for (int j = 0; j < 4; j++) o[df][j] = 0.f;

    const float* mrow = mask + (((size_t)(b * H_ + h)) * L_ + mbase + row0) * N_ + 2 * t4;
    float* Pw = sm + w * (16 * PSTR);   // aliases this warp's Q rows (dead)

    for (int nt = 0; nt < N_ / 128; nt++) {
        // ---- mask prefetch into registers (overlaps wait + S mma) ----
        float2 mk0[16], mk1[16];
        {
            const float* mp = mrow + (size_t)nt * 128;
            #pragma unroll
            for (int nf = 0; nf < 16; nf++) {
                mk0[nf] = *reinterpret_cast<const float2*>(mp + nf * 8);
                mk1[nf] = *reinterpret_cast<const float2*>(mp + (size_t)8 * N_ + nf * 8);
            }
        }

        if (nt < 15) cp_wait<1>(); else cp_wait<0>();
        __syncthreads();
        const float* Ks = sm + OF_K + (nt & 1) * KTILE;
        const float* Vs = sm + OF_V + (nt & 1) * VTILE;

        // ---- S = Q K^T ----
        float s[16][4];
        #pragma unroll
        for (int nf = 0; nf < 16; nf++) {
            s[nf][0] = 0.f; s[nf][1] = 0.f; s[nf][2] = 0.f; s[nf][3] = 0.f;
            #pragma unroll
            for (int k8 = 0; k8 < 8; k8++) {
                uint32_t bf[2];
                bf[0] = __float_as_uint(Ks[(nf * 8 + g) * KSTR + k8 * 8 + t4]);
                bf[1] = __float_as_uint(Ks[(nf * 8 + g) * KSTR + k8 * 8 + t4 + 4]);
                mma_tf32(s[nf], qa[k8], bf);
            }
        }

        // ---- += mask (registers), row-max ----
        float tm0 = -1e30f, tm1 = -1e30f;
        #pragma unroll
        for (int nf = 0; nf < 16; nf++) {
            s[nf][0] += mk0[nf].x;  s[nf][1] += mk0[nf].y;
            s[nf][2] += mk1[nf].x;  s[nf][3] += mk1[nf].y;
            tm0 = fmaxf(tm0, fmaxf(s[nf][0], s[nf][1]));
            tm1 = fmaxf(tm1, fmaxf(s[nf][2], s[nf][3]));
        }
        tm0 = fmaxf(tm0, __shfl_xor_sync(0xffffffffu, tm0, 1));
        tm0 = fmaxf(tm0, __shfl_xor_sync(0xffffffffu, tm0, 2));
        tm1 = fmaxf(tm1, __shfl_xor_sync(0xffffffffu, tm1, 1));
        tm1 = fmaxf(tm1, __shfl_xor_sync(0xffffffffu, tm1, 2));

        float nm0 = fmaxf(m0, tm0), nm1 = fmaxf(m1, tm1);
        float al0 = __expf(m0 - nm0), al1 = __expf(m1 - nm1);
        m0 = nm0; m1 = nm1;

        float rs0 = 0.f, rs1 = 0.f;
        #pragma unroll
        for (int nf = 0; nf < 16; nf++) {
            s[nf][0] = __expf(s[nf][0] - nm0);
            s[nf][1] = __expf(s[nf][1] - nm0);
            s[nf][2] = __expf(s[nf][2] - nm1);
            s[nf][3] = __expf(s[nf][3] - nm1);
            rs0 += s[nf][0] + s[nf][1];
            rs1 += s[nf][2] + s[nf][3];
        }
        rs0 += __shfl_xor_sync(0xffffffffu, rs0, 1);
        rs0 += __shfl_xor_sync(0xffffffffu, rs0, 2);
        rs1 += __shfl_xor_sync(0xffffffffu, rs1, 1);
        rs1 += __shfl_xor_sync(0xffffffffu, rs1, 2);
        l0 = l0 * al0 + rs0;
        l1 = l1 * al1 + rs1;
        #pragma unroll
        for (int df = 0; df < 8; df++) {
            o[df][0] *= al0; o[df][1] *= al0;
            o[df][2] *= al1; o[df][3] *= al1;
        }

        // ---- O += P V in two 64-key halves (P half in warp-private smem) ----
        #pragma unroll
        for (int h2 = 0; h2 < 2; h2++) {
            #pragma unroll
            for (int nf = 0; nf < 8; nf++) {
                int nfg = h2 * 8 + nf;
                float2 p0 = make_float2(f2tf32f(s[nfg][0]), f2tf32f(s[nfg][1]));
                float2 p1 = make_float2(f2tf32f(s[nfg][2]), f2tf32f(s[nfg][3]));
                *reinterpret_cast<float2*>(Pw + g       * PSTR + nf * 8 + 2 * t4) = p0;
                *reinterpret_cast<float2*>(Pw + (g + 8) * PSTR + nf * 8 + 2 * t4) = p1;
            }
            __syncwarp();
            #pragma unroll
            for (int k8 = 0; k8 < 8; k8++) {
                uint32_t pa[4];
                pa[0] = __float_as_uint(Pw[g       * PSTR + k8 * 8 + t4]);
                pa[1] = __float_as_uint(Pw[(g + 8) * PSTR + k8 * 8 + t4]);
                pa[2] = __float_as_uint(Pw[g       * PSTR + k8 * 8 + t4 + 4]);
                pa[3] = __float_as_uint(Pw[(g + 8) * PSTR + k8 * 8 + t4 + 4]);
                int kk = h2 * 64 + k8 * 8;
                #pragma unroll
                for (int df = 0; df < 8; df++) {
                    uint32_t bf[2];
                    bf[0] = __float_as_uint(Vs[(kk + t4)     * VSTR + df * 8 + g]);
                    bf[1] = __float_as_uint(Vs[(kk + t4 + 4) * VSTR + df * 8 + g]);
                    mma_tf32(o[df], pa, bf);
                }
            }
            __syncwarp();   // reads done before next half overwrites P
        }

        __syncthreads();   // all warps done with this K/V stage
        if (nt + 2 < N_ / 128) issueKV(nt + 2, nt & 1);
    }

    // ---- normalize + write ----
    float inv0 = 1.f / l0, inv1 = 1.f / l1;
    float* ob = out + ((size_t)(b * L_ + mbase + row0)) * HID_ + h * HD_;
    #pragma unroll
    for (int df = 0; df < 8; df++) {
        int col = df * 8 + 2 * t4;
        *reinterpret_cast<float2*>(ob + col)                    = make_float2(o[df][0] * inv0, o[df][1] * inv0);
        *reinterpret_cast<float2*>(ob + (size_t)8 * HID_ + col) = make_float2(o[df][2] * inv1, o[df][3] * inv1);
    }
}

// ======================================================================
extern "C" void kernel_launch(void* const* d_in, const int* in_sizes, int n_in,
                              void* d_out, int out_size)
{
    (void)in_sizes; (void)n_in; (void)out_size;
    const float* x     = (const float*)d_in[0];
    const float* vf    = (const float*)d_in[1];
    const float* mask  = (const float*)d_in[2];
    const float* Wq    = (const float*)d_in[3];
    const float* Wkv   = (const float*)d_in[4];
    const float* Wproj = (const float*)d_in[5];
    const float* bproj = (const float*)d_in[6];
    float* out = (float*)d_out;

    float *qbuf, *kvbuf, *aobuf;
    cudaGetSymbolAddress((void**)&qbuf,  g_q);
    cudaGetSymbolAddress((void**)&kvbuf, g_kv);
    cudaGetSymbolAddress((void**)&aobuf, g_ao);

    cudaFuncSetAttribute(qkv_proj_kernel, cudaFuncAttributeMaxDynamicSharedMemorySize, GEMM_SMEM_BYTES);
    cudaFuncSetAttribute(proj_kernel,     cudaFuncAttributeMaxDynamicSharedMemorySize, GEMM_SMEM_BYTES);
    cudaFuncSetAttribute(attn_kernel,     cudaFuncAttributeMaxDynamicSharedMemorySize, ATTN_SMEM_BYTES);

    // Q (128 blocks) + KV (512 blocks) merged
    qkv_proj_kernel<<<640, 256, GEMM_SMEM_BYTES>>>(x, Wq, qbuf, vf, Wkv, kvbuf);

    // fused flash attention with streamed mask
    attn_kernel<<<dim3(L_ / 128, H_, B_), 256, ATTN_SMEM_BYTES>>>(qbuf, kvbuf, mask, aobuf);

    // out = AO @ Wproj^T + bproj
    proj_kernel<<<dim3((VD_ / GBN) * ((B_ * L_) / GBM)), 256, GEMM_SMEM_BYTES>>>(aobuf, Wproj, out, bproj);
}